// round 15
// baseline (speedup 1.0000x reference)
#include <cuda_runtime.h>
#include <math.h>

struct RectD {
    float ABx, ABy, BCx, BCy;   // edge vectors
    float Ax, Ay, Bx, By;       // A, B corners
    float ABAB, BCBC;           // squared lengths
};

__device__ __forceinline__ bool in_rect(float px, float py, const RectD& r) {
    const float eps = 0.01f;
    float AMx = px - r.Ax, AMy = py - r.Ay;
    float BMx = px - r.Bx, BMy = py - r.By;
    float ABAM = r.ABx * AMx + r.ABy * AMy;
    float BCBM = r.BCx * BMx + r.BCy * BMy;
    return (0.0f <= ABAM + eps) & (ABAM <= r.ABAB + eps) &
           (0.0f <= BCBM + eps) & (BCBM <= r.BCBC + eps);
}

__global__ void __launch_bounds__(128)
obb_iou_kernel(const float* __restrict__ b1, const float* __restrict__ b2,
               float* __restrict__ out, int n) {
    // Per-warp candidate store: [warp][point][lane] -> bank == lane, so both
    // the linear writes and the per-lane dynamic reads are conflict-free.
    // 2 * 4*24*32*4B = 24 KB/block; 4 resident blocks = 96 KB (< 228 KB).
    __shared__ float spx[4][24][32];
    __shared__ float spy[4][24][32];

    int i = blockIdx.x * blockDim.x + threadIdx.x;
    if (i >= n) return;

    int lane = threadIdx.x & 31;
    float* wx = &spx[threadIdx.x >> 5][0][lane];
    float* wy = &spy[threadIdx.x >> 5][0][lane];

    // Load 4 corners of each rect (coord0 = "x" in line_intersection, coord1 = "y")
    float4 q0 = reinterpret_cast<const float4*>(b1)[i * 2 + 0];
    float4 q1 = reinterpret_cast<const float4*>(b1)[i * 2 + 1];
    float4 q2 = reinterpret_cast<const float4*>(b2)[i * 2 + 0];
    float4 q3 = reinterpret_cast<const float4*>(b2)[i * 2 + 1];

    float r1x[4] = {q0.x, q0.z, q1.x, q1.z};
    float r1y[4] = {q0.y, q0.w, q1.y, q1.w};
    float r2x[4] = {q2.x, q2.z, q3.x, q3.z};
    float r2y[4] = {q2.y, q2.w, q3.y, q3.w};

    RectD R1, R2;
    R1.Ax = r1x[0]; R1.Ay = r1y[0]; R1.Bx = r1x[1]; R1.By = r1y[1];
    R1.ABx = r1x[1] - r1x[0]; R1.ABy = r1y[1] - r1y[0];
    R1.BCx = r1x[2] - r1x[1]; R1.BCy = r1y[2] - r1y[1];
    R1.ABAB = R1.ABx * R1.ABx + R1.ABy * R1.ABy;
    R1.BCBC = R1.BCx * R1.BCx + R1.BCy * R1.BCy;
    R2.Ax = r2x[0]; R2.Ay = r2y[0]; R2.Bx = r2x[1]; R2.By = r2y[1];
    R2.ABx = r2x[1] - r2x[0]; R2.ABy = r2y[1] - r2y[0];
    R2.BCx = r2x[2] - r2x[1]; R2.BCy = r2y[2] - r2y[1];
    R2.ABAB = R2.ABx * R2.ABx + R2.ABy * R2.ABy;
    R2.BCBC = R2.BCx * R2.BCx + R2.BCy * R2.BCy;

    // 24 candidate points: 16 edge-edge line intersections + rect1 corners + rect2 corners
    float px[24], py[24];
    unsigned int mbits = 0;   // bit a = candidate a passes both in-rect tests

    #pragma unroll
    for (int e1 = 0; e1 < 4; e1++) {
        float x1 = r1x[e1], y1 = r1y[e1];
        float x2 = r1x[(e1 + 1) & 3], y2 = r1y[(e1 + 1) & 3];
        float A  = x1 * y2 - y1 * x2;
        float dx1 = x1 - x2, dy1 = y1 - y2;
        #pragma unroll
        for (int e2 = 0; e2 < 4; e2++) {
            float x3 = r2x[e2], y3 = r2y[e2];
            float x4 = r2x[(e2 + 1) & 3], y4 = r2y[(e2 + 1) & 3];
            float B  = x3 * y4 - y3 * x4;
            float dx2 = x3 - x4, dy2 = y3 - y4;
            float den = dx1 * dy2 - dy1 * dx2;
            if (fabsf(den) < 1e-12f) den = 1e-12f;
            float inv = 1.0f / den;
            float Px = (A * dx2 - dx1 * B) * inv;
            float Py = (A * dy2 - dy1 * B) * inv;
            int k = e1 * 4 + e2;
            px[k] = Px; py[k] = Py;
            wx[k * 32] = Px; wy[k * 32] = Py;
            if (in_rect(Px, Py, R1) & in_rect(Px, Py, R2)) mbits |= (1u << k);
        }
    }
    #pragma unroll
    for (int v = 0; v < 4; v++) {
        px[16 + v] = r1x[v]; py[16 + v] = r1y[v];
        wx[(16 + v) * 32] = r1x[v]; wy[(16 + v) * 32] = r1y[v];
        if (in_rect(r1x[v], r1y[v], R2)) mbits |= (1u << (16 + v));
        px[20 + v] = r2x[v]; py[20 + v] = r2y[v];
        wx[(20 + v) * 32] = r2x[v]; wy[(20 + v) * 32] = r2y[v];
        if (in_rect(r2x[v], r2y[v], R1)) mbits |= (1u << (20 + v));
    }

    // Duplicate suppression (reference tril(-1) semantics): point a loses its
    // mask bit if any earlier point is within L1 dist < 0.01.
    // min-tree form: identical boolean result, cheaper SASS.
    // Intra-rect corner pairs skipped: corners of one rect are >= 2.0 apart in
    // L1 (wh in [2,10]) and can never trip the 0.01 threshold.
    #pragma unroll
    for (int a = 1; a < 24; a++) {
        float dmin = 1e30f;
        #pragma unroll
        for (int b = 0; b < a; b++) {
            if (a >= 16 && b >= 16 && ((a < 20) == (b < 20))) continue;
            dmin = fminf(dmin, fabsf(px[a] - px[b]) + fabsf(py[a] - py[b]));
        }
        if (dmin < 0.01f) mbits &= ~(1u << a);
    }

    int nmask = __popc(mbits);
    int nm8 = nmask < 8 ? nmask : 8;   // top_k keeps at most 8 ones

    // --- Stable top-8 extract via ffs chain + dynamic SMEM reads ---
    // Slot j takes the (j+1)-th set bit of mbits (ascending index = jax
    // top_k's stable permutation on a 0/1 key). Fill slots forced to exactly
    // 0.0f, matching the verified zero-fill semantics (covers the nmask==0
    // NaN-candidate corner: fill must not inherit a possibly-NaN point).
    // Masked points are provably finite (NaN fails every in_rect compare).
    float kx[8], ky[8];
    {
        unsigned int m = mbits;
        #pragma unroll
        for (int j = 0; j < 8; j++) {
            bool valid = (m != 0u);
            int idx = valid ? (__ffs(m) - 1) : 0;
            float X = wx[idx * 32];
            float Y = wy[idx * 32];
            kx[j] = valid ? X : 0.0f;
            ky[j] = valid ? Y : 0.0f;
            m &= m - 1u;
        }
    }

    // convex_polygon_area: blend fill slots to origin (m is exactly 0/1 in the
    // reference, so m*k+(1-m)*o is a select); centroid over masked only (fill
    // slots are exactly 0.0, so plain sums equal the masked sums).
    float ox = kx[0], oy = ky[0];
    float ppx[8], ppy[8];
    float sx = 0.0f, sy = 0.0f;
    #pragma unroll
    for (int a = 0; a < 8; a++) {
        bool m = (a < nm8);
        ppx[a] = m ? kx[a] : ox;
        ppy[a] = m ? ky[a] : oy;
        sx += kx[a]; sy += ky[a];
    }
    float cinv = 1.0f / ((float)nm8 + 1e-6f);
    float cx = sx * cinv, cy = sy * cinv;

    // Diamond pseudo-angle: strictly monotone in atan2(ppx, ppy).
    // Cyclic order identical to sorting by true angle; fan-area with |.| over
    // a convex polygon is invariant to which vertex starts the cycle.
    float ang[8];
    #pragma unroll
    for (int a = 0; a < 8; a++) {
        float A = ppx[a] - cx;
        float B = ppy[a] - cy;
        ppx[a] = A; ppy[a] = B;
        float s = fabsf(A) + fabsf(B);
        float r = __fdividef(A, s);
        r = (s == 0.0f) ? 0.0f : r;
        ang[a] = (B >= 0.0f) ? r : ((A >= 0.0f) ? 2.0f - r : -2.0f - r);
    }

    // Batcher odd-even mergesort network for 8 (19 compare-exchanges).
    // Strict '>' never swaps equal keys; equal keys here have identical coords.
    {
        const int net[19][2] = {
            {0,1},{2,3},{0,2},{1,3},{1,2},          // sort 0..3
            {4,5},{6,7},{4,6},{5,7},{5,6},          // sort 4..7
            {0,4},{1,5},{2,6},{3,7},{2,4},{3,5},    // merge
            {1,2},{3,4},{5,6}
        };
        #pragma unroll
        for (int s = 0; s < 19; s++) {
            int u = net[s][0], v = net[s][1];
            bool sw = ang[u] > ang[v];
            float t;
            t = sw ? ang[v] : ang[u];  ang[v] = sw ? ang[u] : ang[v];  ang[u] = t;
            t = sw ? ppx[v] : ppx[u];  ppx[v] = sw ? ppx[u] : ppx[v];  ppx[u] = t;
            t = sw ? ppy[v] : ppy[u];  ppy[v] = sw ? ppy[u] : ppy[v];  ppy[u] = t;
        }
    }

    // Fan triangulation area (coords already centered). y = coord0, x = coord1.
    float Y0 = ppx[0], X0 = ppy[0];
    float inter = 0.0f;
    #pragma unroll
    for (int a = 1; a < 7; a++) {
        float Y1 = ppx[a],     X1 = ppy[a];
        float Y2 = ppx[a + 1], X2 = ppy[a + 1];
        inter += 0.5f * fabsf(Y0 * (X1 - X2) + Y1 * (X2 - X0) + Y2 * (X0 - X1));
    }

    // Rectangle areas: |y1(x2-x3)+y2(x3-x1)+y3(x1-x2)| with y=coord0, x=coord1
    float a1 = fabsf(r1x[0] * (r1y[1] - r1y[2]) +
                     r1x[1] * (r1y[2] - r1y[0]) +
                     r1x[2] * (r1y[0] - r1y[1]));
    float a2 = fabsf(r2x[0] * (r2y[1] - r2y[2]) +
                     r2x[1] * (r2y[2] - r2y[0]) +
                     r2x[2] * (r2y[0] - r2y[1]));

    out[i] = inter / (a1 + a2 - inter);
}

extern "C" void kernel_launch(void* const* d_in, const int* in_sizes, int n_in,
                              void* d_out, int out_size) {
    const float* b1 = (const float*)d_in[0];
    const float* b2 = (const float*)d_in[1];
    float* out = (float*)d_out;
    int n = in_sizes[0] / 8;   // (N, 4, 2) floats
    int threads = 128;
    int blocks = (n + threads - 1) / threads;
    obb_iou_kernel<<<blocks, threads>>>(b1, b2, out, n);
}

// round 16
// speedup vs baseline: 1.5768x; 1.5768x over previous
#include <cuda_runtime.h>
#include <math.h>

struct RectD {
    float ABx, ABy, BCx, BCy;   // edge vectors
    float Ax, Ay, Bx, By;       // A, B corners
    float ABAB, BCBC;           // squared lengths
};

__device__ __forceinline__ bool in_rect(float px, float py, const RectD& r) {
    const float eps = 0.01f;
    float AMx = px - r.Ax, AMy = py - r.Ay;
    float BMx = px - r.Bx, BMy = py - r.By;
    float ABAM = r.ABx * AMx + r.ABy * AMy;
    float BCBM = r.BCx * BMx + r.BCy * BMy;
    return (0.0f <= ABAM + eps) & (ABAM <= r.ABAB + eps) &
           (0.0f <= BCBM + eps) & (BCBM <= r.BCBC + eps);
}

__global__ void __launch_bounds__(128)
obb_iou_kernel(const float* __restrict__ b1, const float* __restrict__ b2,
               float* __restrict__ out, int n) {
    // Per-warp candidate store: [warp][point][lane] -> bank == lane, so both
    // the linear writes and the per-lane dynamic reads are conflict-free.
    // 2 * 4*24*32*4B = 24 KB/block; 4 resident blocks = 96 KB (< 228 KB).
    __shared__ float spx[4][24][32];
    __shared__ float spy[4][24][32];

    int i = blockIdx.x * blockDim.x + threadIdx.x;
    if (i >= n) return;

    int lane = threadIdx.x & 31;
    float* wx = &spx[threadIdx.x >> 5][0][lane];
    float* wy = &spy[threadIdx.x >> 5][0][lane];

    // Load 4 corners of each rect (coord0 = "x" in line_intersection, coord1 = "y")
    float4 q0 = reinterpret_cast<const float4*>(b1)[i * 2 + 0];
    float4 q1 = reinterpret_cast<const float4*>(b1)[i * 2 + 1];
    float4 q2 = reinterpret_cast<const float4*>(b2)[i * 2 + 0];
    float4 q3 = reinterpret_cast<const float4*>(b2)[i * 2 + 1];

    float r1x[4] = {q0.x, q0.z, q1.x, q1.z};
    float r1y[4] = {q0.y, q0.w, q1.y, q1.w};
    float r2x[4] = {q2.x, q2.z, q3.x, q3.z};
    float r2y[4] = {q2.y, q2.w, q3.y, q3.w};

    RectD R1, R2;
    R1.Ax = r1x[0]; R1.Ay = r1y[0]; R1.Bx = r1x[1]; R1.By = r1y[1];
    R1.ABx = r1x[1] - r1x[0]; R1.ABy = r1y[1] - r1y[0];
    R1.BCx = r1x[2] - r1x[1]; R1.BCy = r1y[2] - r1y[1];
    R1.ABAB = R1.ABx * R1.ABx + R1.ABy * R1.ABy;
    R1.BCBC = R1.BCx * R1.BCx + R1.BCy * R1.BCy;
    R2.Ax = r2x[0]; R2.Ay = r2y[0]; R2.Bx = r2x[1]; R2.By = r2y[1];
    R2.ABx = r2x[1] - r2x[0]; R2.ABy = r2y[1] - r2y[0];
    R2.BCx = r2x[2] - r2x[1]; R2.BCy = r2y[2] - r2y[1];
    R2.ABAB = R2.ABx * R2.ABx + R2.ABy * R2.ABy;
    R2.BCBC = R2.BCx * R2.BCx + R2.BCy * R2.BCy;

    // 24 candidate points: 16 edge-edge line intersections + rect1 corners + rect2 corners
    float px[24], py[24];
    unsigned int mbits = 0;   // bit a = candidate a passes both in-rect tests

    #pragma unroll
    for (int e1 = 0; e1 < 4; e1++) {
        float x1 = r1x[e1], y1 = r1y[e1];
        float x2 = r1x[(e1 + 1) & 3], y2 = r1y[(e1 + 1) & 3];
        float A  = x1 * y2 - y1 * x2;
        float dx1 = x1 - x2, dy1 = y1 - y2;
        #pragma unroll
        for (int e2 = 0; e2 < 4; e2++) {
            float x3 = r2x[e2], y3 = r2y[e2];
            float x4 = r2x[(e2 + 1) & 3], y4 = r2y[(e2 + 1) & 3];
            float B  = x3 * y4 - y3 * x4;
            float dx2 = x3 - x4, dy2 = y3 - y4;
            float den = dx1 * dy2 - dy1 * dx2;
            if (fabsf(den) < 1e-12f) den = 1e-12f;
            float inv = 1.0f / den;
            float Px = (A * dx2 - dx1 * B) * inv;
            float Py = (A * dy2 - dy1 * B) * inv;
            int k = e1 * 4 + e2;
            px[k] = Px; py[k] = Py;
            wx[k * 32] = Px; wy[k * 32] = Py;
            if (in_rect(Px, Py, R1) & in_rect(Px, Py, R2)) mbits |= (1u << k);
        }
    }
    #pragma unroll
    for (int v = 0; v < 4; v++) {
        px[16 + v] = r1x[v]; py[16 + v] = r1y[v];
        wx[(16 + v) * 32] = r1x[v]; wy[(16 + v) * 32] = r1y[v];
        if (in_rect(r1x[v], r1y[v], R2)) mbits |= (1u << (16 + v));
        px[20 + v] = r2x[v]; py[20 + v] = r2y[v];
        wx[(20 + v) * 32] = r2x[v]; wy[(20 + v) * 32] = r2y[v];
        if (in_rect(r2x[v], r2y[v], R1)) mbits |= (1u << (20 + v));
    }

    // Duplicate suppression (reference tril(-1) semantics): point a loses its
    // mask bit if any earlier point is within L1 dist < 0.01.
    // min-tree form: identical boolean result, cheaper SASS.
    // Intra-rect corner pairs skipped: corners of one rect are >= 2.0 apart in
    // L1 (wh in [2,10]) and can never trip the 0.01 threshold.
    #pragma unroll
    for (int a = 1; a < 24; a++) {
        float dmin = 1e30f;
        #pragma unroll
        for (int b = 0; b < a; b++) {
            if (a >= 16 && b >= 16 && ((a < 20) == (b < 20))) continue;
            dmin = fminf(dmin, fabsf(px[a] - px[b]) + fabsf(py[a] - py[b]));
        }
        if (dmin < 0.01f) mbits &= ~(1u << a);
    }

    int nmask = __popc(mbits);
    int nm8 = nmask < 8 ? nmask : 8;   // top_k keeps at most 8 ones

    // --- Stable top-8 extract via ffs chain + dynamic SMEM reads ---
    // Slot j takes the (j+1)-th set bit of mbits (ascending index = jax
    // top_k's stable permutation on a 0/1 key). Fill slots forced to exactly
    // 0.0f, matching the verified zero-fill semantics (covers the nmask==0
    // NaN-candidate corner: fill must not inherit a possibly-NaN point).
    // Masked points are provably finite (NaN fails every in_rect compare).
    float kx[8], ky[8];
    {
        unsigned int m = mbits;
        #pragma unroll
        for (int j = 0; j < 8; j++) {
            bool valid = (m != 0u);
            int idx = valid ? (__ffs(m) - 1) : 0;
            float X = wx[idx * 32];
            float Y = wy[idx * 32];
            kx[j] = valid ? X : 0.0f;
            ky[j] = valid ? Y : 0.0f;
            m &= m - 1u;
        }
    }

    // convex_polygon_area: blend fill slots to origin (m is exactly 0/1 in the
    // reference, so m*k+(1-m)*o is a select); centroid over masked only (fill
    // slots are exactly 0.0, so plain sums equal the masked sums).
    float ox = kx[0], oy = ky[0];
    float ppx[8], ppy[8];
    float sx = 0.0f, sy = 0.0f;
    #pragma unroll
    for (int a = 0; a < 8; a++) {
        bool m = (a < nm8);
        ppx[a] = m ? kx[a] : ox;
        ppy[a] = m ? ky[a] : oy;
        sx += kx[a]; sy += ky[a];
    }
    float cinv = 1.0f / ((float)nm8 + 1e-6f);
    float cx = sx * cinv, cy = sy * cinv;

    // Diamond pseudo-angle: strictly monotone in atan2(ppx, ppy).
    // Cyclic order identical to sorting by true angle; fan-area with |.| over
    // a convex polygon is invariant to which vertex starts the cycle.
    float ang[8];
    #pragma unroll
    for (int a = 0; a < 8; a++) {
        float A = ppx[a] - cx;
        float B = ppy[a] - cy;
        ppx[a] = A; ppy[a] = B;
        float s = fabsf(A) + fabsf(B);
        float r = __fdividef(A, s);
        r = (s == 0.0f) ? 0.0f : r;
        ang[a] = (B >= 0.0f) ? r : ((A >= 0.0f) ? 2.0f - r : -2.0f - r);
    }

    // Batcher odd-even mergesort network for 8 (19 compare-exchanges).
    // Strict '>' never swaps equal keys; equal keys here have identical coords.
    {
        const int net[19][2] = {
            {0,1},{2,3},{0,2},{1,3},{1,2},          // sort 0..3
            {4,5},{6,7},{4,6},{5,7},{5,6},          // sort 4..7
            {0,4},{1,5},{2,6},{3,7},{2,4},{3,5},    // merge
            {1,2},{3,4},{5,6}
        };
        #pragma unroll
        for (int s = 0; s < 19; s++) {
            int u = net[s][0], v = net[s][1];
            bool sw = ang[u] > ang[v];
            float t;
            t = sw ? ang[v] : ang[u];  ang[v] = sw ? ang[u] : ang[v];  ang[u] = t;
            t = sw ? ppx[v] : ppx[u];  ppx[v] = sw ? ppx[u] : ppx[v];  ppx[u] = t;
            t = sw ? ppy[v] : ppy[u];  ppy[v] = sw ? ppy[u] : ppy[v];  ppy[u] = t;
        }
    }

    // Fan triangulation area (coords already centered). y = coord0, x = coord1.
    float Y0 = ppx[0], X0 = ppy[0];
    float inter = 0.0f;
    #pragma unroll
    for (int a = 1; a < 7; a++) {
        float Y1 = ppx[a],     X1 = ppy[a];
        float Y2 = ppx[a + 1], X2 = ppy[a + 1];
        inter += 0.5f * fabsf(Y0 * (X1 - X2) + Y1 * (X2 - X0) + Y2 * (X0 - X1));
    }

    // Rectangle areas: |y1(x2-x3)+y2(x3-x1)+y3(x1-x2)| with y=coord0, x=coord1
    float a1 = fabsf(r1x[0] * (r1y[1] - r1y[2]) +
                     r1x[1] * (r1y[2] - r1y[0]) +
                     r1x[2] * (r1y[0] - r1y[1]));
    float a2 = fabsf(r2x[0] * (r2y[1] - r2y[2]) +
                     r2x[1] * (r2y[2] - r2y[0]) +
                     r2x[2] * (r2y[0] - r2y[1]));

    out[i] = inter / (a1 + a2 - inter);
}

extern "C" void kernel_launch(void* const* d_in, const int* in_sizes, int n_in,
                              void* d_out, int out_size) {
    const float* b1 = (const float*)d_in[0];
    const float* b2 = (const float*)d_in[1];
    float* out = (float*)d_out;
    int n = in_sizes[0] / 8;   // (N, 4, 2) floats
    int threads = 128;
    int blocks = (n + threads - 1) / threads;
    obb_iou_kernel<<<blocks, threads>>>(b1, b2, out, n);
}